// round 3
// baseline (speedup 1.0000x reference)
#include <cuda_runtime.h>
#include <cuda_fp16.h>
#include <stdint.h>

#define TOKENS 8192
#define IN_F   4096
#define OUT_F  11008

// ---------------- scratch (device globals; no allocation allowed) -----------
__device__ __align__(16) float  g_sa[IN_F];
__device__ __align__(16) __half g_xdeq[(size_t)TOKENS * IN_F];   // 64 MB
__device__ __align__(16) __half g_wdeq[(size_t)OUT_F  * IN_F];   // 88 MB
__device__ int g_sw_mode;     // 0 = f16, 1 = f32, 2 = bf16
__device__ int g_pw_is_i32;   // packed_w delivered as int32-per-byte

// ============================================================================
// Kernel 0: input dtype detection (harness upcasts f16->? and uint8->int32).
// s_w reference values are uniform(0.005, 0.02):
//  - if stored bf16, every bf16-read is plausible (f32-stored fails at even
//    indices: low mantissa bits -> garbage exponents).
//  - else if f32-read plausible -> f32.
//  - else f16.
// packed_w: 64 consecutive int32 all in [0,255] => int32-encoded bytes.
// ============================================================================
__global__ void detect_kernel(const void* __restrict__ s_w,
                              const void* __restrict__ pw) {
    // --- s_w ---
    bool bf_ok = true;
    const uint16_t* u16 = (const uint16_t*)s_w;
#pragma unroll
    for (int i = 0; i < 16; ++i) {
        uint32_t bits = ((uint32_t)u16[i]) << 16;
        float v = __uint_as_float(bits);
        bf_ok = bf_ok && isfinite(v) && (v > 1e-4f) && (v < 0.5f);
    }
    bool f32_ok = true;
    const float* f = (const float*)s_w;
#pragma unroll
    for (int i = 0; i < 8; ++i) {
        float v = f[i];
        f32_ok = f32_ok && isfinite(v) && (v > 1e-4f) && (v < 0.5f);
    }
    g_sw_mode = bf_ok ? 2 : (f32_ok ? 1 : 0);

    // --- packed_w ---
    const int* pi = (const int*)pw;
    bool i32_ok = true;
#pragma unroll
    for (int i = 0; i < 64; ++i) {
        int v = pi[i];
        i32_ok = i32_ok && (v >= 0) && (v <= 255);
    }
    g_pw_is_i32 = i32_ok ? 1 : 0;
}

// ============================================================================
// Kernel 1: per-column 0.999 quantile of |x| -> activation scale s_a
// ============================================================================
__global__ void quantile_kernel(const float* __restrict__ x) {
    __shared__ float tops[256][10];
    const int t     = threadIdx.x;
    const int cl    = t & 63;
    const int chunk = t >> 6;
    const int col   = blockIdx.x * 64 + cl;

    const float* p = x + (size_t)chunk * 2048 * IN_F + col;

    float tt[10];
#pragma unroll
    for (int i = 0; i < 10; ++i) tt[i] = -1.0f;

#pragma unroll 4
    for (int r = 0; r < 2048; ++r) {
        float v = fabsf(p[(size_t)r * IN_F]);
        if (v > tt[9]) {
            tt[9] = v;
#pragma unroll
            for (int j = 9; j > 0; --j) {
                if (tt[j] > tt[j - 1]) { float tmp = tt[j - 1]; tt[j - 1] = tt[j]; tt[j] = tmp; }
            }
        }
    }
#pragma unroll
    for (int i = 0; i < 10; ++i) tops[t][i] = tt[i];
    __syncthreads();

    if (chunk == 0) {
        int pi[4] = {0, 0, 0, 0};
        float v9th = 0.f, v10th = 0.f;
        for (int i = 0; i < 10; ++i) {
            int   best = 0;
            float bv   = tops[cl][pi[0]];
#pragma unroll
            for (int j = 1; j < 4; ++j) {
                float c = tops[cl + 64 * j][pi[j]];
                if (c > bv) { bv = c; best = j; }
            }
            pi[best]++;
            if (i == 8) v9th  = bv;
            if (i == 9) v10th = bv;
        }
        // jnp.quantile: pos = 0.999*8191 in (8182, 8183); ascending idx 8183
        // is the 9th largest, 8182 the 10th largest.
        float pos = 0.999f * 8191.0f;
        float qv  = v10th * (8183.0f - pos) + v9th * (pos - 8182.0f);

        float s = fmaxf(qv, 1e-6f) / 127.0f;
        s = fmaxf(s, 1e-6f);
        s = __half2float(__float2half_rn(s));   // fp16 round-trip like reference
        g_sa[col] = s;
    }
}

// ============================================================================
// Kernel 2: fake-quant x -> fp16 x_deq.  One thread = 4 elements (float4).
// ============================================================================
__global__ void quant_x_kernel(const float* __restrict__ x) {
    size_t i = (size_t)blockIdx.x * blockDim.x + threadIdx.x;   // float4 index
    float4 xv = reinterpret_cast<const float4*>(x)[i];
    float4 sv = reinterpret_cast<const float4*>(g_sa)[i & (IN_F / 4 - 1)];

    float q0 = fminf(fmaxf(rintf(xv.x / sv.x), -127.f), 127.f);
    float q1 = fminf(fmaxf(rintf(xv.y / sv.y), -127.f), 127.f);
    float q2 = fminf(fmaxf(rintf(xv.z / sv.z), -127.f), 127.f);
    float q3 = fminf(fmaxf(rintf(xv.w / sv.w), -127.f), 127.f);

    union { __half2 h2[2]; uint2 u; } pk;
    pk.h2[0] = __halves2half2(__float2half_rn(q0 * sv.x), __float2half_rn(q1 * sv.y));
    pk.h2[1] = __halves2half2(__float2half_rn(q2 * sv.z), __float2half_rn(q3 * sv.w));
    reinterpret_cast<uint2*>(g_xdeq)[i] = pk.u;
}

// ============================================================================
// Kernel 3: int4 unpack + scale -> fp16 w_deq.  One thread = 4 packed bytes
// (whether raw uint8 or int32-encoded), producing 8 halves (one uint4).
// ============================================================================
__global__ void dequant_w_kernel(const void* __restrict__ pw,
                                 const void* __restrict__ s_w) {
    size_t i = (size_t)blockIdx.x * blockDim.x + threadIdx.x;  // 4-byte group idx
    int b4[4];
    if (g_pw_is_i32) {
        int4 v = reinterpret_cast<const int4*>(pw)[i];
        b4[0] = v.x & 0xFF; b4[1] = v.y & 0xFF; b4[2] = v.z & 0xFF; b4[3] = v.w & 0xFF;
    } else {
        uint32_t w = reinterpret_cast<const uint32_t*>(pw)[i];
        b4[0] = w & 0xFF; b4[1] = (w >> 8) & 0xFF; b4[2] = (w >> 16) & 0xFF; b4[3] = (w >> 24) & 0xFF;
    }
    int o = (int)(i >> 9);                       // 512 groups per output row
    float sw;
    int mode = g_sw_mode;
    if (mode == 1)      sw = ((const float*)s_w)[o];
    else if (mode == 2) sw = __uint_as_float(((uint32_t)((const uint16_t*)s_w)[o]) << 16);
    else                sw = __half2float(((const __half*)s_w)[o]);

    union { __half2 h2[4]; uint4 u; } pk;
#pragma unroll
    for (int j = 0; j < 4; ++j) {
        int b  = b4[j];
        int lo = b & 15;  lo = (lo >= 8) ? lo - 16 : lo;
        int hi = b >> 4;  hi = (hi >= 8) ? hi - 16 : hi;
        pk.h2[j] = __halves2half2(__float2half_rn((float)lo * sw),
                                  __float2half_rn((float)hi * sw));
    }
    reinterpret_cast<uint4*>(g_wdeq)[i] = pk.u;
}

// ============================================================================
// Kernel 4: GEMM  out[8192,11008] = x_deq @ w_deq^T + bias
// 128x128x32 tile, 256 threads (2x4 warps), double-buffered cp.async +
// ldmatrix + mma.sync.m16n8k16 f16f16f32.
// ============================================================================
#define GBM 128
#define GBN 128
#define GBK 32
#define GST 40      // smem row stride in halves (32 + 8 pad)

__global__ void __launch_bounds__(256)
gemm_kernel(const float* __restrict__ bias, float* __restrict__ out) {
    __shared__ __align__(16) __half As[2][GBM * GST];
    __shared__ __align__(16) __half Bs[2][GBN * GST];

    const int bn = blockIdx.x, bm = blockIdx.y;
    const int tid  = threadIdx.x;
    const int warp = tid >> 5, lane = tid & 31;
    const int wm = warp >> 2, wn = warp & 3;

    const __half* Ag = g_xdeq + (size_t)(bm * GBM) * IN_F;
    const __half* Bg = g_wdeq + (size_t)(bn * GBN) * IN_F;

    const uint32_t as_base = (uint32_t)__cvta_generic_to_shared(&As[0][0]);
    const uint32_t bs_base = (uint32_t)__cvta_generic_to_shared(&Bs[0][0]);

    float acc[4][4][4];
#pragma unroll
    for (int mt = 0; mt < 4; ++mt)
#pragma unroll
        for (int nt = 0; nt < 4; ++nt)
#pragma unroll
            for (int r = 0; r < 4; ++r) acc[mt][nt][r] = 0.f;

    auto load_tile = [&](int kt, int buf) {
#pragma unroll
        for (int h = 0; h < 2; ++h) {
            int c    = tid + h * 256;
            int row  = c >> 2;
            int col8 = (c & 3) * 8;
            const __half* ga = Ag + (size_t)row * IN_F + kt * GBK + col8;
            uint32_t sa = as_base + (uint32_t)(buf * GBM * GST + row * GST + col8) * 2u;
            asm volatile("cp.async.cg.shared.global [%0], [%1], 16;\n" :: "r"(sa), "l"(ga));
            const __half* gb = Bg + (size_t)row * IN_F + kt * GBK + col8;
            uint32_t sb = bs_base + (uint32_t)(buf * GBN * GST + row * GST + col8) * 2u;
            asm volatile("cp.async.cg.shared.global [%0], [%1], 16;\n" :: "r"(sb), "l"(gb));
        }
    };

    auto compute = [&](int buf) {
        const int g   = lane >> 3;
        const int idx = lane & 7;
#pragma unroll
        for (int kk = 0; kk < GBK; kk += 16) {
            uint32_t a[4][4];
#pragma unroll
            for (int mt = 0; mt < 4; ++mt) {
                int row = wm * 64 + mt * 16 + idx + (g & 1) * 8;
                int col = kk + (g >> 1) * 8;
                uint32_t addr = as_base + (uint32_t)(buf * GBM * GST + row * GST + col) * 2u;
                asm volatile("ldmatrix.sync.aligned.m8n8.x4.shared.b16 {%0,%1,%2,%3}, [%4];\n"
                             : "=r"(a[mt][0]), "=r"(a[mt][1]), "=r"(a[mt][2]), "=r"(a[mt][3])
                             : "r"(addr));
            }
            uint32_t b[2][4];
#pragma unroll
            for (int bt = 0; bt < 2; ++bt) {
                int n   = wn * 32 + bt * 16 + idx + (g >> 1) * 8;
                int col = kk + (g & 1) * 8;
                uint32_t addr = bs_base + (uint32_t)(buf * GBN * GST + n * GST + col) * 2u;
                asm volatile("ldmatrix.sync.aligned.m8n8.x4.shared.b16 {%0,%1,%2,%3}, [%4];\n"
                             : "=r"(b[bt][0]), "=r"(b[bt][1]), "=r"(b[bt][2]), "=r"(b[bt][3])
                             : "r"(addr));
            }
#pragma unroll
            for (int mt = 0; mt < 4; ++mt) {
#pragma unroll
                for (int nt = 0; nt < 4; ++nt) {
                    uint32_t b0 = b[nt >> 1][(nt & 1) * 2];
                    uint32_t b1 = b[nt >> 1][(nt & 1) * 2 + 1];
                    asm volatile(
                        "mma.sync.aligned.m16n8k16.row.col.f32.f16.f16.f32 "
                        "{%0,%1,%2,%3}, {%4,%5,%6,%7}, {%8,%9}, {%0,%1,%2,%3};\n"
                        : "+f"(acc[mt][nt][0]), "+f"(acc[mt][nt][1]),
                          "+f"(acc[mt][nt][2]), "+f"(acc[mt][nt][3])
                        : "r"(a[mt][0]), "r"(a[mt][1]), "r"(a[mt][2]), "r"(a[mt][3]),
                          "r"(b0), "r"(b1));
                }
            }
        }
    };

    const int NT = IN_F / GBK;   // 128
    load_tile(0, 0);
    asm volatile("cp.async.commit_group;\n");
    asm volatile("cp.async.wait_group 0;\n");
    __syncthreads();

    for (int kt = 0; kt < NT; ++kt) {
        int cur = kt & 1;
        if (kt + 1 < NT) {
            load_tile(kt + 1, cur ^ 1);
            asm volatile("cp.async.commit_group;\n");
        }
        compute(cur);
        if (kt + 1 < NT) asm volatile("cp.async.wait_group 0;\n");
        __syncthreads();
    }

#pragma unroll
    for (int nt = 0; nt < 4; ++nt) {
        int c0 = bn * GBN + wn * 32 + nt * 8 + (lane & 3) * 2;
        float b0 = bias[c0], b1 = bias[c0 + 1];
#pragma unroll
        for (int mt = 0; mt < 4; ++mt) {
            int r0 = bm * GBM + wm * 64 + mt * 16 + (lane >> 2);
            float2 v0 = make_float2(acc[mt][nt][0] + b0, acc[mt][nt][1] + b1);
            float2 v1 = make_float2(acc[mt][nt][2] + b0, acc[mt][nt][3] + b1);
            *reinterpret_cast<float2*>(out + (size_t)r0 * OUT_F + c0)       = v0;
            *reinterpret_cast<float2*>(out + (size_t)(r0 + 8) * OUT_F + c0) = v1;
        }
    }
}

// ============================================================================
// launch
// ============================================================================
extern "C" void kernel_launch(void* const* d_in, const int* in_sizes, int n_in,
                              void* d_out, int out_size) {
    const float* x    = (const float*)d_in[0];
    const void*  pw   = (const void*)d_in[1];
    const void*  s_w  = (const void*)d_in[2];
    const float* bias = (const float*)d_in[3];
    float*       out  = (float*)d_out;

    detect_kernel<<<1, 1>>>(s_w, pw);
    quantile_kernel<<<IN_F / 64, 256>>>(x);
    quant_x_kernel<<<(TOKENS * IN_F / 4) / 256, 256>>>(x);
    dequant_w_kernel<<<(OUT_F * (IN_F / 2) / 4) / 256, 256>>>(pw, s_w);
    gemm_kernel<<<dim3(OUT_F / GBN, TOKENS / GBM), 256>>>(bias, out);
}